// round 1
// baseline (speedup 1.0000x reference)
#include <cuda_runtime.h>
#include <cuda_bf16.h>
#include <cstdint>

// Problem constants (fixed by the dataset)
#define NN 50000
#define EE 400000
#define HH 2
#define DD 128
#define HD 256          // HH*DD
#define ET 450000       // EE + NN (self loops appended)
#define NEG_SLOPE 0.2f

// ---------------- scratch (static device memory; no allocation allowed) ----
__device__ float    g_xl[(size_t)NN * HD];
__device__ float    g_xr[(size_t)NN * HD];
__device__ float    g_agg[(size_t)NN * HD];
__device__ float    g_score[(size_t)ET * HH];
__device__ float    g_denom[(size_t)NN * HH];
__device__ unsigned g_mord[(size_t)NN * HH];
__device__ int      g_src[ET];
__device__ int      g_dst[ET];
__device__ int      g_is64;

// ---------------- helpers --------------------------------------------------
__device__ __forceinline__ float lrelu(float v) {
    return v > 0.f ? v : NEG_SLOPE * v;
}
// order-preserving float -> uint encoding for atomicMax
__device__ __forceinline__ unsigned f2ord(float f) {
    unsigned u = __float_as_uint(f);
    return (u & 0x80000000u) ? ~u : (u | 0x80000000u);
}
__device__ __forceinline__ float ord2f(unsigned u) {
    return (u & 0x80000000u) ? __uint_as_float(u & 0x7FFFFFFFu)
                             : __uint_as_float(~u);
}
__device__ __forceinline__ void red_add_v4(float* p, float4 v) {
    asm volatile("red.global.add.v4.f32 [%0], {%1,%2,%3,%4};"
                 :: "l"(p), "f"(v.x), "f"(v.y), "f"(v.z), "f"(v.w)
                 : "memory");
}

// ---------------- edge dtype detection + conversion ------------------------
// If edge_index is int64 (little-endian, values < 50000), every odd 32-bit
// word of the buffer is zero. With int32 data those words are indices
// (P(all 256 zero) ~ (1/50000)^256 = 0).
__global__ void detect_dtype_kernel(const unsigned* __restrict__ w) {
    unsigned v = w[2 * threadIdx.x + 1];
    int any = __syncthreads_or(v != 0u);
    if (threadIdx.x == 0) g_is64 = (any == 0) ? 1 : 0;
}

__global__ void convert_edges_kernel(const void* __restrict__ ei) {
    int e = blockIdx.x * blockDim.x + threadIdx.x;
    if (e >= ET) return;
    if (e < EE) {
        if (g_is64) {
            const long long* p = (const long long*)ei;
            g_src[e] = (int)p[e];
            g_dst[e] = (int)p[EE + e];
        } else {
            const int* p = (const int*)ei;
            g_src[e] = p[e];
            g_dst[e] = p[EE + e];
        }
    } else {
        g_src[e] = e - EE;   // self loop
        g_dst[e] = e - EE;
    }
}

// ---------------- init scratch ---------------------------------------------
__global__ void init_kernel() {
    int stride = gridDim.x * blockDim.x;
    for (int i = blockIdx.x * blockDim.x + threadIdx.x; i < NN * HD; i += stride)
        g_agg[i] = 0.f;
    for (int i = blockIdx.x * blockDim.x + threadIdx.x; i < NN * HH; i += stride) {
        g_denom[i] = 0.f;
        g_mord[i]  = 0u;      // encodes below every float
    }
}

// ---------------- SGEMM: C[M,OUT] = (A[M,K] + abias) @ W[OUT,K]^T + bias ---
// BM=BN=128, BK=8, 256 threads, 8x8 per thread.
__global__ __launch_bounds__(256)
void sgemm_kernel(const float* __restrict__ A, const float* __restrict__ W,
                  const float* __restrict__ bias, const float* __restrict__ abias,
                  float* __restrict__ C, int M, int K, int OUT) {
    __shared__ float As[8][128];
    __shared__ float Bs[8][128];

    const int tid = threadIdx.x;
    const int rowBlock = blockIdx.x * 128;
    const int colBlock = blockIdx.y * 128;
    const int loadRow = tid >> 1;         // 0..127
    const int loadCol = (tid & 1) * 4;    // 0 or 4
    const int ty = tid >> 4;              // 0..15
    const int tx = tid & 15;              // 0..15

    float acc[8][8];
#pragma unroll
    for (int i = 0; i < 8; i++)
#pragma unroll
        for (int j = 0; j < 8; j++) acc[i][j] = 0.f;

    for (int k0 = 0; k0 < K; k0 += 8) {
        // --- load A tile (with optional per-k bias on A) ---
        int arow = rowBlock + loadRow;
        float4 a = make_float4(0.f, 0.f, 0.f, 0.f);
        if (arow < M) {
            a = *(const float4*)(A + (size_t)arow * K + k0 + loadCol);
            if (abias) {
                a.x += abias[k0 + loadCol + 0];
                a.y += abias[k0 + loadCol + 1];
                a.z += abias[k0 + loadCol + 2];
                a.w += abias[k0 + loadCol + 3];
            }
        }
        As[loadCol + 0][loadRow] = a.x;
        As[loadCol + 1][loadRow] = a.y;
        As[loadCol + 2][loadRow] = a.z;
        As[loadCol + 3][loadRow] = a.w;

        // --- load W tile (OUT is always a multiple of 128 here) ---
        float4 b = *(const float4*)(W + (size_t)(colBlock + loadRow) * K + k0 + loadCol);
        Bs[loadCol + 0][loadRow] = b.x;
        Bs[loadCol + 1][loadRow] = b.y;
        Bs[loadCol + 2][loadRow] = b.z;
        Bs[loadCol + 3][loadRow] = b.w;

        __syncthreads();

#pragma unroll
        for (int kk = 0; kk < 8; kk++) {
            float regA[8], regB[8];
            *(float4*)&regA[0] = *(const float4*)&As[kk][ty * 8];
            *(float4*)&regA[4] = *(const float4*)&As[kk][ty * 8 + 4];
            *(float4*)&regB[0] = *(const float4*)&Bs[kk][tx * 8];
            *(float4*)&regB[4] = *(const float4*)&Bs[kk][tx * 8 + 4];
#pragma unroll
            for (int i = 0; i < 8; i++)
#pragma unroll
                for (int j = 0; j < 8; j++)
                    acc[i][j] = fmaf(regA[i], regB[j], acc[i][j]);
        }
        __syncthreads();
    }

    // --- store with bias ---
#pragma unroll
    for (int i = 0; i < 8; i++) {
        int row = rowBlock + ty * 8 + i;
        if (row >= M) continue;
        int col = colBlock + tx * 8;
        float4 o0, o1;
        o0.x = acc[i][0] + bias[col + 0];
        o0.y = acc[i][1] + bias[col + 1];
        o0.z = acc[i][2] + bias[col + 2];
        o0.w = acc[i][3] + bias[col + 3];
        o1.x = acc[i][4] + bias[col + 4];
        o1.y = acc[i][5] + bias[col + 5];
        o1.z = acc[i][6] + bias[col + 6];
        o1.w = acc[i][7] + bias[col + 7];
        *(float4*)(C + (size_t)row * OUT + col)     = o0;
        *(float4*)(C + (size_t)row * OUT + col + 4) = o1;
    }
}

// ---------------- pass 1: edge score + segment max -------------------------
// one warp per (edge, head)
__global__ __launch_bounds__(256)
void score_kernel(const float* __restrict__ att) {
    int w = (blockIdx.x * blockDim.x + threadIdx.x) >> 5;
    int lane = threadIdx.x & 31;
    if (w >= ET * HH) return;
    int e = w >> 1;
    int h = w & 1;
    int s = g_src[e];
    int d = g_dst[e];
    int off = h * DD + lane * 4;

    float4 a  = *(const float4*)(g_xl + (size_t)s * HD + off);
    float4 b  = *(const float4*)(g_xr + (size_t)d * HD + off);
    float4 av = *(const float4*)(att + off);

    float sum = lrelu(a.x + b.x) * av.x + lrelu(a.y + b.y) * av.y +
                lrelu(a.z + b.z) * av.z + lrelu(a.w + b.w) * av.w;
#pragma unroll
    for (int o = 16; o; o >>= 1) sum += __shfl_xor_sync(0xFFFFFFFFu, sum, o);

    if (lane == 0) {
        g_score[w] = sum;
        atomicMax(&g_mord[d * HH + h], f2ord(sum));
    }
}

// ---------------- pass 2: exp + segment sum --------------------------------
__global__ __launch_bounds__(256)
void expsum_kernel() {
    int t = blockIdx.x * blockDim.x + threadIdx.x;
    if (t >= ET * HH) return;
    int e = t >> 1;
    int h = t & 1;
    int d = g_dst[e];
    float m = ord2f(g_mord[d * HH + h]);
    float a = __expf(g_score[t] - m);
    g_score[t] = a;
    atomicAdd(&g_denom[d * HH + h], a);
}

// ---------------- pass 3: weighted aggregation -----------------------------
// one warp per (edge, head)
__global__ __launch_bounds__(256)
void aggregate_kernel() {
    int w = (blockIdx.x * blockDim.x + threadIdx.x) >> 5;
    int lane = threadIdx.x & 31;
    if (w >= ET * HH) return;
    int e = w >> 1;
    int h = w & 1;
    int s = g_src[e];
    int d = g_dst[e];
    float alpha = g_score[w] / (g_denom[d * HH + h] + 1e-16f);
    int off = h * DD + lane * 4;

    float4 v = *(const float4*)(g_xl + (size_t)s * HD + off);
    v.x *= alpha; v.y *= alpha; v.z *= alpha; v.w *= alpha;
    red_add_v4(g_agg + (size_t)d * HD + off, v);
}

// ---------------- launch ---------------------------------------------------
extern "C" void kernel_launch(void* const* d_in, const int* in_sizes, int n_in,
                              void* d_out, int out_size) {
    const float* x         = (const float*)d_in[0];
    const void*  edge      = d_in[1];
    const float* Wl        = (const float*)d_in[2];
    const float* bl        = (const float*)d_in[3];
    const float* Wr        = (const float*)d_in[4];
    const float* br        = (const float*)d_in[5];
    const float* att       = (const float*)d_in[6];
    const float* bias_conv = (const float*)d_in[7];
    const float* Wo        = (const float*)d_in[8];
    const float* bo        = (const float*)d_in[9];
    float* out = (float*)d_out;

    float* xl;   cudaGetSymbolAddress((void**)&xl,  g_xl);
    float* xr;   cudaGetSymbolAddress((void**)&xr,  g_xr);
    float* agg;  cudaGetSymbolAddress((void**)&agg, g_agg);

    // 1. detect edge dtype + build int32 src/dst with self loops
    detect_dtype_kernel<<<1, 256>>>((const unsigned*)edge);
    convert_edges_kernel<<<(ET + 255) / 256, 256>>>(edge);

    // 2. init scratch
    init_kernel<<<1024, 256>>>();

    // 3. node projections: xl = x@Wl^T+bl, xr = x@Wr^T+br   [N, 256]
    {
        dim3 grid((NN + 127) / 128, HD / 128);
        sgemm_kernel<<<grid, 256>>>(x, Wl, bl, nullptr, xl, NN, DD, HD);
        sgemm_kernel<<<grid, 256>>>(x, Wr, br, nullptr, xr, NN, DD, HD);
    }

    // 4. edge scores + segment max (one warp per edge-head)
    {
        int warps = ET * HH;                       // 900000
        int blocks = (warps * 32 + 255) / 256;     // 112500
        score_kernel<<<blocks, 256>>>(att);
    }

    // 5. exp + segment sum
    expsum_kernel<<<(ET * HH + 255) / 256, 256>>>();

    // 6. weighted aggregation into g_agg
    {
        int warps = ET * HH;
        int blocks = (warps * 32 + 255) / 256;
        aggregate_kernel<<<blocks, 256>>>();
    }

    // 7. output projection: out = (agg + bias_conv) @ Wo^T + bo   [N, 128]
    {
        dim3 grid((NN + 127) / 128, DD / 128);
        sgemm_kernel<<<grid, 256>>>(agg, Wo, bo, bias_conv, out, NN, HD, DD);
    }
}

// round 2
// speedup vs baseline: 1.6549x; 1.6549x over previous
#include <cuda_runtime.h>
#include <cuda_bf16.h>
#include <cstdint>

// Problem constants (fixed by the dataset)
#define NN 50000
#define EE 400000
#define HH 2
#define DD 128
#define HD 256          // HH*DD
#define ET 450000       // EE + NN (self loops appended)
#define NEG_SLOPE 0.2f

// ---------------- scratch (static device memory; no allocation allowed) ----
__device__ float    g_xl[(size_t)NN * HD];
__device__ float    g_xr[(size_t)NN * HD];
__device__ float    g_agg[(size_t)NN * HD];
__device__ float    g_score[(size_t)ET * HH];   // exp(score)
__device__ float    g_denom[(size_t)NN * HH];
__device__ int      g_src[ET];
__device__ int      g_dst[ET];
__device__ int      g_is64;

// ---------------- helpers --------------------------------------------------
__device__ __forceinline__ float lrelu(float v) {
    return v > 0.f ? v : NEG_SLOPE * v;
}
__device__ __forceinline__ void red_add_v4(float* p, float4 v) {
    asm volatile("red.global.add.v4.f32 [%0], {%1,%2,%3,%4};"
                 :: "l"(p), "f"(v.x), "f"(v.y), "f"(v.z), "f"(v.w)
                 : "memory");
}
__device__ __forceinline__ uint32_t f2tf32(float f) {
    uint32_t u;
    asm("cvt.rna.tf32.f32 %0, %1;" : "=r"(u) : "f"(f));
    return u;
}
__device__ __forceinline__ void mma_tf32(float c[4], const uint32_t a[4],
                                         const uint32_t b[2]) {
    asm volatile(
        "mma.sync.aligned.m16n8k8.row.col.f32.tf32.tf32.f32 "
        "{%0,%1,%2,%3}, {%4,%5,%6,%7}, {%8,%9}, {%0,%1,%2,%3};"
        : "+f"(c[0]), "+f"(c[1]), "+f"(c[2]), "+f"(c[3])
        : "r"(a[0]), "r"(a[1]), "r"(a[2]), "r"(a[3]), "r"(b[0]), "r"(b[1]));
}

// ---------------- edge dtype detection + conversion ------------------------
__global__ void detect_dtype_kernel(const unsigned* __restrict__ w) {
    unsigned v = w[2 * threadIdx.x + 1];
    int any = __syncthreads_or(v != 0u);
    if (threadIdx.x == 0) g_is64 = (any == 0) ? 1 : 0;
}

__global__ void convert_edges_kernel(const void* __restrict__ ei) {
    int e = blockIdx.x * blockDim.x + threadIdx.x;
    if (e >= ET) return;
    if (e < EE) {
        if (g_is64) {
            const long long* p = (const long long*)ei;
            g_src[e] = (int)p[e];
            g_dst[e] = (int)p[EE + e];
        } else {
            const int* p = (const int*)ei;
            g_src[e] = p[e];
            g_dst[e] = p[EE + e];
        }
    } else {
        g_src[e] = e - EE;   // self loop
        g_dst[e] = e - EE;
    }
}

// ---------------- init scratch ---------------------------------------------
__global__ void init_kernel() {
    int stride = gridDim.x * blockDim.x;
    for (int i = blockIdx.x * blockDim.x + threadIdx.x; i < NN * HD; i += stride)
        g_agg[i] = 0.f;
    for (int i = blockIdx.x * blockDim.x + threadIdx.x; i < NN * HH; i += stride)
        g_denom[i] = 0.f;
}

// ---------------- TF32 tensor-core GEMM ------------------------------------
// C[M,OUT] = (A[M,K] + abias) @ W[OUT,K]^T + bias
// BM=BN=128, BK=16, 256 threads (8 warps, 2x4), each warp 64x32 via m16n8k8.
#define SMS 20   // smem row stride (floats), conflict-free for frag loads
__global__ __launch_bounds__(256, 2)
void tf32_gemm_kernel(const float* __restrict__ A, const float* __restrict__ W,
                      const float* __restrict__ bias,
                      const float* __restrict__ abias,
                      float* __restrict__ C, int M, int K, int OUT) {
    __shared__ uint32_t As[128 * SMS];
    __shared__ uint32_t Bs[128 * SMS];

    const int tid  = threadIdx.x;
    const int lane = tid & 31;
    const int wid  = tid >> 5;
    const int warpM = wid & 1;        // 0..1 -> 64-row half
    const int warpN = wid >> 1;       // 0..3 -> 32-col quarter
    const int gp = lane >> 2;         // 0..7
    const int tg = lane & 3;          // 0..3
    const int rowBlock = blockIdx.x * 128;
    const int colBlock = blockIdx.y * 128;

    const int lr = tid >> 2;          // 0..63 (row within half-tile)
    const int lc = (tid & 3) * 4;     // k col 0/4/8/12

    float acc[4][4][4];
#pragma unroll
    for (int mt = 0; mt < 4; mt++)
#pragma unroll
        for (int nt = 0; nt < 4; nt++)
#pragma unroll
            for (int r = 0; r < 4; r++) acc[mt][nt][r] = 0.f;

    for (int k0 = 0; k0 < K; k0 += 16) {
#pragma unroll
        for (int h = 0; h < 2; h++) {
            int row  = lr + h * 64;
            // A tile (guarded rows; optional A-side bias)
            int grow = rowBlock + row;
            float4 a = make_float4(0.f, 0.f, 0.f, 0.f);
            if (grow < M) {
                a = *(const float4*)(A + (size_t)grow * K + k0 + lc);
                if (abias) {
                    a.x += abias[k0 + lc + 0];
                    a.y += abias[k0 + lc + 1];
                    a.z += abias[k0 + lc + 2];
                    a.w += abias[k0 + lc + 3];
                }
            }
            uint32_t* pa = &As[row * SMS + lc];
            pa[0] = f2tf32(a.x); pa[1] = f2tf32(a.y);
            pa[2] = f2tf32(a.z); pa[3] = f2tf32(a.w);
            // W tile (OUT is a multiple of 128, no guard needed)
            float4 b = *(const float4*)(W + (size_t)(colBlock + row) * K + k0 + lc);
            uint32_t* pb = &Bs[row * SMS + lc];
            pb[0] = f2tf32(b.x); pb[1] = f2tf32(b.y);
            pb[2] = f2tf32(b.z); pb[3] = f2tf32(b.w);
        }
        __syncthreads();

#pragma unroll
        for (int kk = 0; kk < 16; kk += 8) {
            uint32_t af[4][4], bf[4][2];
#pragma unroll
            for (int mt = 0; mt < 4; mt++) {
                int m0 = warpM * 64 + mt * 16;
                af[mt][0] = As[(m0 + gp)     * SMS + kk + tg];
                af[mt][1] = As[(m0 + gp + 8) * SMS + kk + tg];
                af[mt][2] = As[(m0 + gp)     * SMS + kk + tg + 4];
                af[mt][3] = As[(m0 + gp + 8) * SMS + kk + tg + 4];
            }
#pragma unroll
            for (int nt = 0; nt < 4; nt++) {
                int n0 = warpN * 32 + nt * 8;
                bf[nt][0] = Bs[(n0 + gp) * SMS + kk + tg];
                bf[nt][1] = Bs[(n0 + gp) * SMS + kk + tg + 4];
            }
#pragma unroll
            for (int mt = 0; mt < 4; mt++)
#pragma unroll
                for (int nt = 0; nt < 4; nt++)
                    mma_tf32(acc[mt][nt], af[mt], bf[nt]);
        }
        __syncthreads();
    }

    // epilogue: add bias, store float2 pairs
#pragma unroll
    for (int mt = 0; mt < 4; mt++) {
#pragma unroll
        for (int nt = 0; nt < 4; nt++) {
            int col  = colBlock + warpN * 32 + nt * 8 + tg * 2;
            float b0 = bias[col], b1 = bias[col + 1];
            int row0 = rowBlock + warpM * 64 + mt * 16 + gp;
            if (row0 < M) {
                float2 o = make_float2(acc[mt][nt][0] + b0, acc[mt][nt][1] + b1);
                *(float2*)(C + (size_t)row0 * OUT + col) = o;
            }
            int row1 = row0 + 8;
            if (row1 < M) {
                float2 o = make_float2(acc[mt][nt][2] + b0, acc[mt][nt][3] + b1);
                *(float2*)(C + (size_t)row1 * OUT + col) = o;
            }
        }
    }
}

// ---------------- pass 1: score -> exp -> denom (fused, no max pass) -------
// one warp per edge, lanes 0-15 = head 0, lanes 16-31 = head 1
__global__ __launch_bounds__(256)
void score_kernel(const float* __restrict__ att) {
    int w = (blockIdx.x * blockDim.x + threadIdx.x) >> 5;
    int lane = threadIdx.x & 31;
    if (w >= ET) return;
    int s = g_src[w];
    int d = g_dst[w];
    int off = lane * 8;

    float4 a0 = *(const float4*)(g_xl + (size_t)s * HD + off);
    float4 a1 = *(const float4*)(g_xl + (size_t)s * HD + off + 4);
    float4 b0 = *(const float4*)(g_xr + (size_t)d * HD + off);
    float4 b1 = *(const float4*)(g_xr + (size_t)d * HD + off + 4);
    float4 v0 = *(const float4*)(att + off);
    float4 v1 = *(const float4*)(att + off + 4);

    float sum = lrelu(a0.x + b0.x) * v0.x + lrelu(a0.y + b0.y) * v0.y +
                lrelu(a0.z + b0.z) * v0.z + lrelu(a0.w + b0.w) * v0.w +
                lrelu(a1.x + b1.x) * v1.x + lrelu(a1.y + b1.y) * v1.y +
                lrelu(a1.z + b1.z) * v1.z + lrelu(a1.w + b1.w) * v1.w;
#pragma unroll
    for (int o = 8; o; o >>= 1) sum += __shfl_xor_sync(0xFFFFFFFFu, sum, o);

    if (lane == 0 || lane == 16) {
        int h = lane >> 4;
        float ex = __expf(fminf(sum, 80.f));
        g_score[w * HH + h] = ex;
        atomicAdd(&g_denom[d * HH + h], ex);
    }
}

// ---------------- pass 2: weighted aggregation -----------------------------
// one warp per edge, both heads
__global__ __launch_bounds__(256)
void aggregate_kernel() {
    int w = (blockIdx.x * blockDim.x + threadIdx.x) >> 5;
    int lane = threadIdx.x & 31;
    if (w >= ET) return;
    int s = g_src[w];
    int d = g_dst[w];
    int h = lane >> 4;
    float alpha = g_score[w * HH + h] / (g_denom[d * HH + h] + 1e-16f);
    int off = lane * 8;

    float4 v0 = *(const float4*)(g_xl + (size_t)s * HD + off);
    float4 v1 = *(const float4*)(g_xl + (size_t)s * HD + off + 4);
    v0.x *= alpha; v0.y *= alpha; v0.z *= alpha; v0.w *= alpha;
    v1.x *= alpha; v1.y *= alpha; v1.z *= alpha; v1.w *= alpha;
    red_add_v4(g_agg + (size_t)d * HD + off,     v0);
    red_add_v4(g_agg + (size_t)d * HD + off + 4, v1);
}

// ---------------- launch ---------------------------------------------------
extern "C" void kernel_launch(void* const* d_in, const int* in_sizes, int n_in,
                              void* d_out, int out_size) {
    const float* x         = (const float*)d_in[0];
    const void*  edge      = d_in[1];
    const float* Wl        = (const float*)d_in[2];
    const float* bl        = (const float*)d_in[3];
    const float* Wr        = (const float*)d_in[4];
    const float* br        = (const float*)d_in[5];
    const float* att       = (const float*)d_in[6];
    const float* bias_conv = (const float*)d_in[7];
    const float* Wo        = (const float*)d_in[8];
    const float* bo        = (const float*)d_in[9];
    float* out = (float*)d_out;

    float* xl;   cudaGetSymbolAddress((void**)&xl,  g_xl);
    float* xr;   cudaGetSymbolAddress((void**)&xr,  g_xr);
    float* agg;  cudaGetSymbolAddress((void**)&agg, g_agg);

    // 1. detect edge dtype + build int32 src/dst with self loops
    detect_dtype_kernel<<<1, 256>>>((const unsigned*)edge);
    convert_edges_kernel<<<(ET + 255) / 256, 256>>>(edge);

    // 2. init scratch
    init_kernel<<<1024, 256>>>();

    // 3. node projections (TF32 tensor cores)
    {
        dim3 grid((NN + 127) / 128, HD / 128);
        tf32_gemm_kernel<<<grid, 256>>>(x, Wl, bl, nullptr, xl, NN, DD, HD);
        tf32_gemm_kernel<<<grid, 256>>>(x, Wr, br, nullptr, xr, NN, DD, HD);
    }

    // 4. edge scores + exp + denom (fused)
    {
        int blocks = (ET * 32 + 255) / 256;   // 56250
        score_kernel<<<blocks, 256>>>(att);
    }

    // 5. weighted aggregation into g_agg
    {
        int blocks = (ET * 32 + 255) / 256;
        aggregate_kernel<<<blocks, 256>>>();
    }

    // 6. output projection: out = (agg + bias_conv) @ Wo^T + bo
    {
        dim3 grid((NN + 127) / 128, DD / 128);
        tf32_gemm_kernel<<<grid, 256>>>(agg, Wo, bo, bias_conv, out, NN, HD, DD);
    }
}

// round 3
// speedup vs baseline: 2.0553x; 1.2420x over previous
#include <cuda_runtime.h>
#include <cuda_bf16.h>
#include <cstdint>

// Problem constants (fixed by the dataset)
#define NN 50000
#define EE 400000
#define HH 2
#define DD 128
#define HD 256          // HH*DD
#define ET 450000       // EE + NN (self loops appended)
#define NEG_SLOPE 0.2f

// ---------------- scratch (static device memory; no allocation allowed) ----
__device__ float g_xl[(size_t)NN * HD];
__device__ float g_xr[(size_t)NN * HD];
__device__ float g_agg[(size_t)NN * HD];
__device__ int   g_src[ET];
__device__ int   g_dst[ET];
__device__ int   g_deg[NN];        // histogram, then reused as scatter cursor
__device__ int   g_off[NN + 1];
__device__ int   g_csr_src[ET];
__device__ float g_bias_eff[DD];
__device__ int   g_is64;

// ---------------- helpers --------------------------------------------------
__device__ __forceinline__ float lrelu(float v) {
    return v > 0.f ? v : NEG_SLOPE * v;
}
__device__ __forceinline__ uint32_t f2tf32(float f) {
    uint32_t u;
    asm("cvt.rna.tf32.f32 %0, %1;" : "=r"(u) : "f"(f));
    return u;
}
__device__ __forceinline__ void mma_tf32(float c[4], const uint32_t a[4],
                                         const uint32_t b[2]) {
    asm volatile(
        "mma.sync.aligned.m16n8k8.row.col.f32.tf32.tf32.f32 "
        "{%0,%1,%2,%3}, {%4,%5,%6,%7}, {%8,%9}, {%0,%1,%2,%3};"
        : "+f"(c[0]), "+f"(c[1]), "+f"(c[2]), "+f"(c[3])
        : "r"(a[0]), "r"(a[1]), "r"(a[2]), "r"(a[3]), "r"(b[0]), "r"(b[1]));
}
#define CP_ASYNC16(dst_smem, src_ptr) \
    asm volatile("cp.async.ca.shared.global [%0], [%1], 16;" \
                 :: "r"(dst_smem), "l"(src_ptr))
#define CP_COMMIT() asm volatile("cp.async.commit_group;")
#define CP_WAIT1()  asm volatile("cp.async.wait_group 1;")
#define CP_WAIT0()  asm volatile("cp.async.wait_group 0;")

// ---------------- edge dtype detection + conversion ------------------------
__global__ void detect_dtype_kernel(const unsigned* __restrict__ w) {
    unsigned v = w[2 * threadIdx.x + 1];
    int any = __syncthreads_or(v != 0u);
    if (threadIdx.x == 0) g_is64 = (any == 0) ? 1 : 0;
}

__global__ void convert_edges_kernel(const void* __restrict__ ei) {
    int e = blockIdx.x * blockDim.x + threadIdx.x;
    if (e >= ET) return;
    if (e < EE) {
        if (g_is64) {
            const long long* p = (const long long*)ei;
            g_src[e] = (int)p[e];
            g_dst[e] = (int)p[EE + e];
        } else {
            const int* p = (const int*)ei;
            g_src[e] = p[e];
            g_dst[e] = p[EE + e];
        }
    } else {
        g_src[e] = e - EE;   // self loop
        g_dst[e] = e - EE;
    }
}

// ---------------- CSR build -------------------------------------------------
__global__ void zero_deg_kernel() {
    int i = blockIdx.x * blockDim.x + threadIdx.x;
    if (i < NN) g_deg[i] = 0;
}
__global__ void hist_kernel() {
    int e = blockIdx.x * blockDim.x + threadIdx.x;
    if (e < ET) atomicAdd(&g_deg[g_dst[e]], 1);
}
// single-block exclusive scan of g_deg -> g_off; also re-zeroes g_deg
__global__ __launch_bounds__(1024)
void scan_kernel() {
    __shared__ int sums[1024];
    const int CH = (NN + 1023) / 1024;   // 49
    int tid = threadIdx.x;
    int base = tid * CH;
    int s = 0;
    for (int i = 0; i < CH; i++) {
        int idx = base + i;
        if (idx < NN) s += g_deg[idx];
    }
    sums[tid] = s;
    __syncthreads();
    for (int o = 1; o < 1024; o <<= 1) {
        int v = (tid >= o) ? sums[tid - o] : 0;
        __syncthreads();
        sums[tid] += v;
        __syncthreads();
    }
    int run = sums[tid] - s;   // exclusive prefix of this thread's chunk
    for (int i = 0; i < CH; i++) {
        int idx = base + i;
        if (idx < NN) {
            g_off[idx] = run;
            run += g_deg[idx];
            g_deg[idx] = 0;    // reuse as scatter cursor
        }
    }
    if (tid == 1023) g_off[NN] = run;
}
__global__ void scatter_kernel() {
    int e = blockIdx.x * blockDim.x + threadIdx.x;
    if (e >= ET) return;
    int d = g_dst[e];
    int pos = atomicAdd(&g_deg[d], 1);
    g_csr_src[g_off[d] + pos] = g_src[e];
}

// ---------------- bias fold: bias_eff = bo + bias_conv @ Wo^T --------------
__global__ void biaseff_kernel(const float* __restrict__ bias_conv,
                               const float* __restrict__ Wo,
                               const float* __restrict__ bo) {
    int c = threadIdx.x;
    if (c >= DD) return;
    float s = bo[c];
    for (int k = 0; k < HD; k++) s += bias_conv[k] * Wo[(size_t)c * HD + k];
    g_bias_eff[c] = s;
}

// ---------------- TF32 tensor-core GEMM (cp.async double-buffered) ---------
// C[M,OUT] = A[M,K] @ W[OUT,K]^T + bias
// BM=BN=128, BK=16, 256 threads (8 warps, 2x4), each warp 64x32 via m16n8k8.
#define SMS 20   // smem row stride (floats), conflict-free fragment loads
__global__ __launch_bounds__(256, 2)
void tf32_gemm_kernel(const float* __restrict__ A, const float* __restrict__ W,
                      const float* __restrict__ bias,
                      float* __restrict__ C, int M, int K, int OUT) {
    __shared__ float As[2][128 * SMS];
    __shared__ float Bs[2][128 * SMS];

    const int tid  = threadIdx.x;
    const int lane = tid & 31;
    const int wid  = tid >> 5;
    const int warpM = wid & 1;
    const int warpN = wid >> 1;
    const int gp = lane >> 2;
    const int tg = lane & 3;
    const int rowBlock = blockIdx.x * 128;
    const int colBlock = blockIdx.y * 128;
    const int lr = tid >> 2;          // 0..63
    const int lc = (tid & 3) * 4;     // 0/4/8/12

    float acc[4][4][4];
#pragma unroll
    for (int mt = 0; mt < 4; mt++)
#pragma unroll
        for (int nt = 0; nt < 4; nt++)
#pragma unroll
            for (int r = 0; r < 4; r++) acc[mt][nt][r] = 0.f;

    auto load_stage = [&](int k0, int buf) {
#pragma unroll
        for (int h = 0; h < 2; h++) {
            int row  = lr + h * 64;
            int grow = rowBlock + row;
            float* sa = &As[buf][row * SMS + lc];
            if (grow < M) {
                CP_ASYNC16((uint32_t)__cvta_generic_to_shared(sa),
                           A + (size_t)grow * K + k0 + lc);
            } else {
                sa[0] = 0.f; sa[1] = 0.f; sa[2] = 0.f; sa[3] = 0.f;
            }
            float* sb = &Bs[buf][row * SMS + lc];
            CP_ASYNC16((uint32_t)__cvta_generic_to_shared(sb),
                       W + (size_t)(colBlock + row) * K + k0 + lc);
        }
    };

    const int nk = K >> 4;
    load_stage(0, 0);
    CP_COMMIT();

    for (int t = 0; t < nk; t++) {
        int cur = t & 1;
        if (t + 1 < nk) {
            load_stage((t + 1) << 4, (t + 1) & 1);
            CP_COMMIT();
            CP_WAIT1();
        } else {
            CP_WAIT0();
        }
        __syncthreads();

#pragma unroll
        for (int kk = 0; kk < 16; kk += 8) {
            uint32_t af[4][4], bf[4][2];
#pragma unroll
            for (int mt = 0; mt < 4; mt++) {
                int m0 = warpM * 64 + mt * 16;
                af[mt][0] = f2tf32(As[cur][(m0 + gp)     * SMS + kk + tg]);
                af[mt][1] = f2tf32(As[cur][(m0 + gp + 8) * SMS + kk + tg]);
                af[mt][2] = f2tf32(As[cur][(m0 + gp)     * SMS + kk + tg + 4]);
                af[mt][3] = f2tf32(As[cur][(m0 + gp + 8) * SMS + kk + tg + 4]);
            }
#pragma unroll
            for (int nt = 0; nt < 4; nt++) {
                int n0 = warpN * 32 + nt * 8;
                bf[nt][0] = f2tf32(Bs[cur][(n0 + gp) * SMS + kk + tg]);
                bf[nt][1] = f2tf32(Bs[cur][(n0 + gp) * SMS + kk + tg + 4]);
            }
#pragma unroll
            for (int mt = 0; mt < 4; mt++)
#pragma unroll
                for (int nt = 0; nt < 4; nt++)
                    mma_tf32(acc[mt][nt], af[mt], bf[nt]);
        }
        __syncthreads();
    }

    // epilogue
#pragma unroll
    for (int mt = 0; mt < 4; mt++) {
#pragma unroll
        for (int nt = 0; nt < 4; nt++) {
            int col  = colBlock + warpN * 32 + nt * 8 + tg * 2;
            float b0 = bias[col], b1 = bias[col + 1];
            int row0 = rowBlock + warpM * 64 + mt * 16 + gp;
            if (row0 < M) {
                float2 o = make_float2(acc[mt][nt][0] + b0, acc[mt][nt][1] + b1);
                *(float2*)(C + (size_t)row0 * OUT + col) = o;
            }
            int row1 = row0 + 8;
            if (row1 < M) {
                float2 o = make_float2(acc[mt][nt][2] + b0, acc[mt][nt][3] + b1);
                *(float2*)(C + (size_t)row1 * OUT + col) = o;
            }
        }
    }
}

// ---------------- fused GAT pass: one warp per destination node -------------
// lanes 0-15 = head 0 (cols 0-127), lanes 16-31 = head 1 (cols 128-255);
// each lane owns 8 contiguous feature columns.
__global__ __launch_bounds__(256)
void gat_fused_kernel(const float* __restrict__ att) {
    int n = (blockIdx.x * blockDim.x + threadIdx.x) >> 5;
    int lane = threadIdx.x & 31;
    if (n >= NN) return;
    int off = lane * 8;

    const float4* pr = (const float4*)(g_xr + (size_t)n * HD + off);
    float4 b0 = pr[0], b1 = pr[1];
    float4 v0 = *(const float4*)(att + off);
    float4 v1 = *(const float4*)(att + off + 4);

    float acc[8] = {0, 0, 0, 0, 0, 0, 0, 0};
    float denom = 0.f;

    int beg = g_off[n], end = g_off[n + 1];
    // prefetch first neighbor (every node has >=1: its self loop)
    int s = g_csr_src[beg];
    const float4* p = (const float4*)(g_xl + (size_t)s * HD + off);
    float4 a0 = p[0], a1 = p[1];

    for (int i = beg; i < end; i++) {
        float4 c0 = a0, c1 = a1;
        if (i + 1 < end) {
            int sn = g_csr_src[i + 1];
            const float4* pn = (const float4*)(g_xl + (size_t)sn * HD + off);
            a0 = pn[0]; a1 = pn[1];
        }
        float t = lrelu(c0.x + b0.x) * v0.x + lrelu(c0.y + b0.y) * v0.y +
                  lrelu(c0.z + b0.z) * v0.z + lrelu(c0.w + b0.w) * v0.w +
                  lrelu(c1.x + b1.x) * v1.x + lrelu(c1.y + b1.y) * v1.y +
                  lrelu(c1.z + b1.z) * v1.z + lrelu(c1.w + b1.w) * v1.w;
#pragma unroll
        for (int o = 8; o; o >>= 1) t += __shfl_xor_sync(0xFFFFFFFFu, t, o);
        float ex = __expf(fminf(t, 80.f));
        acc[0] = fmaf(ex, c0.x, acc[0]);
        acc[1] = fmaf(ex, c0.y, acc[1]);
        acc[2] = fmaf(ex, c0.z, acc[2]);
        acc[3] = fmaf(ex, c0.w, acc[3]);
        acc[4] = fmaf(ex, c1.x, acc[4]);
        acc[5] = fmaf(ex, c1.y, acc[5]);
        acc[6] = fmaf(ex, c1.z, acc[6]);
        acc[7] = fmaf(ex, c1.w, acc[7]);
        denom += ex;
    }

    float inv = 1.f / (denom + 1e-16f);
    float4 o0 = make_float4(acc[0] * inv, acc[1] * inv, acc[2] * inv, acc[3] * inv);
    float4 o1 = make_float4(acc[4] * inv, acc[5] * inv, acc[6] * inv, acc[7] * inv);
    float4* po = (float4*)(g_agg + (size_t)n * HD + off);
    po[0] = o0;
    po[1] = o1;
}

// ---------------- launch ---------------------------------------------------
extern "C" void kernel_launch(void* const* d_in, const int* in_sizes, int n_in,
                              void* d_out, int out_size) {
    const float* x         = (const float*)d_in[0];
    const void*  edge      = d_in[1];
    const float* Wl        = (const float*)d_in[2];
    const float* bl        = (const float*)d_in[3];
    const float* Wr        = (const float*)d_in[4];
    const float* br        = (const float*)d_in[5];
    const float* att       = (const float*)d_in[6];
    const float* bias_conv = (const float*)d_in[7];
    const float* Wo        = (const float*)d_in[8];
    const float* bo        = (const float*)d_in[9];
    float* out = (float*)d_out;

    float* xl;   cudaGetSymbolAddress((void**)&xl,   g_xl);
    float* xr;   cudaGetSymbolAddress((void**)&xr,   g_xr);
    float* agg;  cudaGetSymbolAddress((void**)&agg,  g_agg);
    float* beff; cudaGetSymbolAddress((void**)&beff, g_bias_eff);

    // 1. edges -> int32 src/dst (+self loops), then CSR by dst
    detect_dtype_kernel<<<1, 256>>>((const unsigned*)edge);
    convert_edges_kernel<<<(ET + 255) / 256, 256>>>(edge);
    zero_deg_kernel<<<(NN + 255) / 256, 256>>>();
    hist_kernel<<<(ET + 255) / 256, 256>>>();
    scan_kernel<<<1, 1024>>>();
    scatter_kernel<<<(ET + 255) / 256, 256>>>();

    // 2. fold bias_conv into output bias
    biaseff_kernel<<<1, 128>>>(bias_conv, Wo, bo);

    // 3. node projections (TF32 tensor cores, cp.async pipelined)
    {
        dim3 grid((NN + 127) / 128, HD / 128);
        tf32_gemm_kernel<<<grid, 256>>>(x, Wl, bl, xl, NN, DD, HD);
        tf32_gemm_kernel<<<grid, 256>>>(x, Wr, br, xr, NN, DD, HD);
    }

    // 4. fused: score -> exp -> weighted aggregate (one warp per node)
    gat_fused_kernel<<<(NN * 32 + 255) / 256, 256>>>(att);

    // 5. output projection: out = agg @ Wo^T + bias_eff
    {
        dim3 grid((NN + 127) / 128, DD / 128);
        tf32_gemm_kernel<<<grid, 256>>>(agg, Wo, beff, out, NN, HD, DD);
    }
}

// round 4
// speedup vs baseline: 2.1538x; 1.0480x over previous
#include <cuda_runtime.h>
#include <cuda_bf16.h>
#include <cstdint>

// Problem constants (fixed by the dataset)
#define NN 50000
#define EE 400000
#define HH 2
#define DD 128
#define HD 256          // HH*DD
#define ET 450000       // EE + NN (self loops appended)
#define NEG_SLOPE 0.2f

// ---------------- scratch (static device memory; no allocation allowed) ----
__device__ float g_xl[(size_t)NN * HD];
__device__ float g_xr[(size_t)NN * HD];
__device__ float g_agg[(size_t)NN * HD];
__device__ int   g_src[ET];
__device__ int   g_dst[ET];
__device__ int   g_deg[NN];        // histogram, then reused as scatter cursor
__device__ int   g_off[NN + 1];
__device__ int   g_csr_src[ET];
__device__ float g_bias_eff[DD];
__device__ int   g_is64;

// ---------------- helpers --------------------------------------------------
__device__ __forceinline__ float lrelu(float v) {
    return v > 0.f ? v : NEG_SLOPE * v;
}
__device__ __forceinline__ uint32_t f2tf32(float f) {
    uint32_t u;
    asm("cvt.rna.tf32.f32 %0, %1;" : "=r"(u) : "f"(f));
    return u;
}
__device__ __forceinline__ void mma_tf32(float c[4], const uint32_t a[4],
                                         const uint32_t b[2]) {
    asm volatile(
        "mma.sync.aligned.m16n8k8.row.col.f32.tf32.tf32.f32 "
        "{%0,%1,%2,%3}, {%4,%5,%6,%7}, {%8,%9}, {%0,%1,%2,%3};"
        : "+f"(c[0]), "+f"(c[1]), "+f"(c[2]), "+f"(c[3])
        : "r"(a[0]), "r"(a[1]), "r"(a[2]), "r"(a[3]), "r"(b[0]), "r"(b[1]));
}
#define CP_ASYNC16(dst_smem, src_ptr) \
    asm volatile("cp.async.ca.shared.global [%0], [%1], 16;" \
                 :: "r"(dst_smem), "l"(src_ptr))
#define CP_COMMIT() asm volatile("cp.async.commit_group;")
#define CP_WAIT1()  asm volatile("cp.async.wait_group 1;")
#define CP_WAIT0()  asm volatile("cp.async.wait_group 0;")

// ---------------- edge prep -------------------------------------------------
__global__ void detect_dtype_kernel(const unsigned* __restrict__ w) {
    unsigned v = w[2 * threadIdx.x + 1];
    int any = __syncthreads_or(v != 0u);
    if (threadIdx.x == 0) g_is64 = (any == 0) ? 1 : 0;
}
__global__ void zero_deg_kernel() {
    int i = blockIdx.x * blockDim.x + threadIdx.x;
    if (i < NN) g_deg[i] = 0;
}
// convert + histogram fused
__global__ void convert_hist_kernel(const void* __restrict__ ei) {
    int e = blockIdx.x * blockDim.x + threadIdx.x;
    if (e >= ET) return;
    int s, d;
    if (e < EE) {
        if (g_is64) {
            const long long* p = (const long long*)ei;
            s = (int)p[e];
            d = (int)p[EE + e];
        } else {
            const int* p = (const int*)ei;
            s = p[e];
            d = p[EE + e];
        }
    } else {
        s = e - EE;   // self loop
        d = e - EE;
    }
    g_src[e] = s;
    g_dst[e] = d;
    atomicAdd(&g_deg[d], 1);
}
// single-block exclusive scan of g_deg -> g_off; also re-zeroes g_deg
__global__ __launch_bounds__(1024)
void scan_kernel() {
    __shared__ int sums[1024];
    const int CH = (NN + 1023) / 1024;   // 49
    int tid = threadIdx.x;
    int base = tid * CH;
    int s = 0;
    for (int i = 0; i < CH; i++) {
        int idx = base + i;
        if (idx < NN) s += g_deg[idx];
    }
    sums[tid] = s;
    __syncthreads();
    for (int o = 1; o < 1024; o <<= 1) {
        int v = (tid >= o) ? sums[tid - o] : 0;
        __syncthreads();
        sums[tid] += v;
        __syncthreads();
    }
    int run = sums[tid] - s;
    for (int i = 0; i < CH; i++) {
        int idx = base + i;
        if (idx < NN) {
            g_off[idx] = run;
            run += g_deg[idx];
            g_deg[idx] = 0;    // reuse as scatter cursor
        }
    }
    if (tid == 1023) g_off[NN] = run;
}
__global__ void scatter_kernel() {
    int e = blockIdx.x * blockDim.x + threadIdx.x;
    if (e >= ET) return;
    int d = g_dst[e];
    int pos = atomicAdd(&g_deg[d], 1);
    g_csr_src[g_off[d] + pos] = g_src[e];
}

// ---------------- bias fold: bias_eff = bo + bias_conv @ Wo^T --------------
__global__ void biaseff_kernel(const float* __restrict__ bias_conv,
                               const float* __restrict__ Wo,
                               const float* __restrict__ bo) {
    int c = threadIdx.x;
    if (c >= DD) return;
    float s = bo[c];
    for (int k = 0; k < HD; k++) s += bias_conv[k] * Wo[(size_t)c * HD + k];
    g_bias_eff[c] = s;
}

// ---------------- TF32 GEMM, dual weight/output sets -----------------------
// For blockIdx.y < ycnt: C0[M,OUT] = A @ W0^T + b0 (col block = y)
// else:                  C1[M,OUT] = A @ W1^T + b1 (col block = y - ycnt)
// BM=BN=128, BK=16, 256 threads (8 warps, 2x4), warp tile 64x32 via m16n8k8.
#define SMS 20
__global__ __launch_bounds__(256, 2)
void tf32_gemm_kernel(const float* __restrict__ A,
                      const float* __restrict__ W0, const float* __restrict__ b0v,
                      float* __restrict__ C0,
                      const float* __restrict__ W1, const float* __restrict__ b1v,
                      float* __restrict__ C1,
                      int M, int K, int OUT, int ycnt) {
    __shared__ float As[2][128 * SMS];
    __shared__ float Bs[2][128 * SMS];

    const float* W;  const float* bias;  float* C;
    int yb = blockIdx.y;
    if (yb < ycnt) { W = W0; bias = b0v; C = C0; }
    else           { W = W1; bias = b1v; C = C1; yb -= ycnt; }

    const int tid  = threadIdx.x;
    const int lane = tid & 31;
    const int wid  = tid >> 5;
    const int warpM = wid & 1;
    const int warpN = wid >> 1;
    const int gp = lane >> 2;
    const int tg = lane & 3;
    const int rowBlock = blockIdx.x * 128;
    const int colBlock = yb * 128;
    const int lr = tid >> 2;          // 0..63
    const int lc = (tid & 3) * 4;     // 0/4/8/12

    float acc[4][4][4];
#pragma unroll
    for (int mt = 0; mt < 4; mt++)
#pragma unroll
        for (int nt = 0; nt < 4; nt++)
#pragma unroll
            for (int r = 0; r < 4; r++) acc[mt][nt][r] = 0.f;

    auto load_stage = [&](int k0, int buf) {
#pragma unroll
        for (int h = 0; h < 2; h++) {
            int row  = lr + h * 64;
            int grow = rowBlock + row;
            float* sa = &As[buf][row * SMS + lc];
            if (grow < M) {
                CP_ASYNC16((uint32_t)__cvta_generic_to_shared(sa),
                           A + (size_t)grow * K + k0 + lc);
            } else {
                sa[0] = 0.f; sa[1] = 0.f; sa[2] = 0.f; sa[3] = 0.f;
            }
            float* sb = &Bs[buf][row * SMS + lc];
            CP_ASYNC16((uint32_t)__cvta_generic_to_shared(sb),
                       W + (size_t)(colBlock + row) * K + k0 + lc);
        }
    };

    const int nk = K >> 4;
    load_stage(0, 0);
    CP_COMMIT();

    for (int t = 0; t < nk; t++) {
        int cur = t & 1;
        if (t + 1 < nk) {
            load_stage((t + 1) << 4, (t + 1) & 1);
            CP_COMMIT();
            CP_WAIT1();
        } else {
            CP_WAIT0();
        }
        __syncthreads();

#pragma unroll
        for (int kk = 0; kk < 16; kk += 8) {
            uint32_t af[4][4], bf[4][2];
#pragma unroll
            for (int mt = 0; mt < 4; mt++) {
                int m0 = warpM * 64 + mt * 16;
                af[mt][0] = f2tf32(As[cur][(m0 + gp)     * SMS + kk + tg]);
                af[mt][1] = f2tf32(As[cur][(m0 + gp + 8) * SMS + kk + tg]);
                af[mt][2] = f2tf32(As[cur][(m0 + gp)     * SMS + kk + tg + 4]);
                af[mt][3] = f2tf32(As[cur][(m0 + gp + 8) * SMS + kk + tg + 4]);
            }
#pragma unroll
            for (int nt = 0; nt < 4; nt++) {
                int n0 = warpN * 32 + nt * 8;
                bf[nt][0] = f2tf32(Bs[cur][(n0 + gp) * SMS + kk + tg]);
                bf[nt][1] = f2tf32(Bs[cur][(n0 + gp) * SMS + kk + tg + 4]);
            }
#pragma unroll
            for (int mt = 0; mt < 4; mt++)
#pragma unroll
                for (int nt = 0; nt < 4; nt++)
                    mma_tf32(acc[mt][nt], af[mt], bf[nt]);
        }
        __syncthreads();
    }

    // epilogue
#pragma unroll
    for (int mt = 0; mt < 4; mt++) {
#pragma unroll
        for (int nt = 0; nt < 4; nt++) {
            int col  = colBlock + warpN * 32 + nt * 8 + tg * 2;
            float bb0 = bias[col], bb1 = bias[col + 1];
            int row0 = rowBlock + warpM * 64 + mt * 16 + gp;
            if (row0 < M) {
                float2 o = make_float2(acc[mt][nt][0] + bb0, acc[mt][nt][1] + bb1);
                *(float2*)(C + (size_t)row0 * OUT + col) = o;
            }
            int row1 = row0 + 8;
            if (row1 < M) {
                float2 o = make_float2(acc[mt][nt][2] + bb0, acc[mt][nt][3] + bb1);
                *(float2*)(C + (size_t)row1 * OUT + col) = o;
            }
        }
    }
}

// ---------------- fused GAT pass: one warp per destination node -------------
// lanes 0-15 = head 0 (cols 0-127), lanes 16-31 = head 1 (cols 128-255);
// each lane owns 8 contiguous feature columns. 2-deep neighbor prefetch.
__global__ __launch_bounds__(256)
void gat_fused_kernel(const float* __restrict__ att) {
    int n = (blockIdx.x * blockDim.x + threadIdx.x) >> 5;
    int lane = threadIdx.x & 31;
    if (n >= NN) return;
    int off = lane * 8;

    const float4* pr = (const float4*)(g_xr + (size_t)n * HD + off);
    float4 b0 = pr[0], b1 = pr[1];
    float4 v0 = *(const float4*)(att + off);
    float4 v1 = *(const float4*)(att + off + 4);

    float acc[8] = {0, 0, 0, 0, 0, 0, 0, 0};
    float denom = 0.f;

    const int beg = g_off[n], end = g_off[n + 1];

    // 2-deep prefetch pipeline (every node has >= 1 neighbor: its self loop)
    float4 A0, A1, B0, B1;
    {
        int s0 = g_csr_src[beg];
        const float4* p0 = (const float4*)(g_xl + (size_t)s0 * HD + off);
        A0 = p0[0]; A1 = p0[1];
    }
    if (beg + 1 < end) {
        int s1 = g_csr_src[beg + 1];
        const float4* p1 = (const float4*)(g_xl + (size_t)s1 * HD + off);
        B0 = p1[0]; B1 = p1[1];
    }

    for (int i = beg; i < end; i++) {
        float4 c0 = A0, c1 = A1;
        A0 = B0; A1 = B1;
        if (i + 2 < end) {
            int sn = g_csr_src[i + 2];
            const float4* pn = (const float4*)(g_xl + (size_t)sn * HD + off);
            B0 = pn[0]; B1 = pn[1];
        }
        float t = lrelu(c0.x + b0.x) * v0.x + lrelu(c0.y + b0.y) * v0.y +
                  lrelu(c0.z + b0.z) * v0.z + lrelu(c0.w + b0.w) * v0.w +
                  lrelu(c1.x + b1.x) * v1.x + lrelu(c1.y + b1.y) * v1.y +
                  lrelu(c1.z + b1.z) * v1.z + lrelu(c1.w + b1.w) * v1.w;
#pragma unroll
        for (int o = 8; o; o >>= 1) t += __shfl_xor_sync(0xFFFFFFFFu, t, o);
        float ex = __expf(fminf(t, 80.f));
        acc[0] = fmaf(ex, c0.x, acc[0]);
        acc[1] = fmaf(ex, c0.y, acc[1]);
        acc[2] = fmaf(ex, c0.z, acc[2]);
        acc[3] = fmaf(ex, c0.w, acc[3]);
        acc[4] = fmaf(ex, c1.x, acc[4]);
        acc[5] = fmaf(ex, c1.y, acc[5]);
        acc[6] = fmaf(ex, c1.z, acc[6]);
        acc[7] = fmaf(ex, c1.w, acc[7]);
        denom += ex;
    }

    float inv = 1.f / (denom + 1e-16f);
    float4 o0 = make_float4(acc[0] * inv, acc[1] * inv, acc[2] * inv, acc[3] * inv);
    float4 o1 = make_float4(acc[4] * inv, acc[5] * inv, acc[6] * inv, acc[7] * inv);
    float4* po = (float4*)(g_agg + (size_t)n * HD + off);
    po[0] = o0;
    po[1] = o1;
}

// ---------------- launch ---------------------------------------------------
extern "C" void kernel_launch(void* const* d_in, const int* in_sizes, int n_in,
                              void* d_out, int out_size) {
    const float* x         = (const float*)d_in[0];
    const void*  edge      = d_in[1];
    const float* Wl        = (const float*)d_in[2];
    const float* bl        = (const float*)d_in[3];
    const float* Wr        = (const float*)d_in[4];
    const float* br        = (const float*)d_in[5];
    const float* att       = (const float*)d_in[6];
    const float* bias_conv = (const float*)d_in[7];
    const float* Wo        = (const float*)d_in[8];
    const float* bo        = (const float*)d_in[9];
    float* out = (float*)d_out;

    float* xl;   cudaGetSymbolAddress((void**)&xl,   g_xl);
    float* xr;   cudaGetSymbolAddress((void**)&xr,   g_xr);
    float* agg;  cudaGetSymbolAddress((void**)&agg,  g_agg);
    float* beff; cudaGetSymbolAddress((void**)&beff, g_bias_eff);

    // 1. edges -> int32 src/dst (+self loops) + degree histogram, then CSR
    detect_dtype_kernel<<<1, 256>>>((const unsigned*)edge);
    zero_deg_kernel<<<(NN + 255) / 256, 256>>>();
    convert_hist_kernel<<<(ET + 255) / 256, 256>>>(edge);
    scan_kernel<<<1, 1024>>>();
    scatter_kernel<<<(ET + 255) / 256, 256>>>();

    // 2. fold bias_conv into output bias
    biaseff_kernel<<<1, 128>>>(bias_conv, Wo, bo);

    // 3. node projections: one merged launch (xl and xr)
    {
        dim3 grid((NN + 127) / 128, 4);
        tf32_gemm_kernel<<<grid, 256>>>(x, Wl, bl, xl, Wr, br, xr,
                                        NN, DD, HD, 2);
    }

    // 4. fused: score -> exp -> weighted aggregate (one warp per node)
    gat_fused_kernel<<<(NN * 32 + 255) / 256, 256>>>(att);

    // 5. output projection: out = agg @ Wo^T + bias_eff
    {
        dim3 grid((NN + 127) / 128, 1);
        tf32_gemm_kernel<<<grid, 256>>>(agg, Wo, beff, out, Wo, beff, out,
                                        NN, HD, DD, 1);
    }
}

// round 5
// speedup vs baseline: 3.1078x; 1.4429x over previous
#include <cuda_runtime.h>
#include <cuda_bf16.h>
#include <cstdint>

// Problem constants (fixed by the dataset)
#define NN 50000
#define EE 400000
#define HH 2
#define DD 128
#define HD 256          // HH*DD
#define ET 450000       // EE + NN (self loops appended)
#define NEG_SLOPE 0.2f
#define NB 196          // (NN + 255) / 256 scan blocks

// ---------------- scratch (static device memory; no allocation allowed) ----
__device__ float g_xl[(size_t)NN * HD];
__device__ float g_xr[(size_t)NN * HD];
__device__ float g_agg[(size_t)NN * HD];
__device__ int   g_src[ET];
__device__ int   g_dst[ET];
__device__ int   g_deg[NN];        // histogram, then reused as scatter cursor
__device__ int   g_off[NN + 1];
__device__ int   g_csr_src[ET];
__device__ int   g_bsum[256];
__device__ int   g_boff[256];
__device__ float g_bias_eff[DD];
__device__ int   g_is64;

// ---------------- helpers --------------------------------------------------
__device__ __forceinline__ float lrelu(float v) {
    return v > 0.f ? v : NEG_SLOPE * v;
}
__device__ __forceinline__ uint32_t f2tf32(float f) {
    uint32_t u;
    asm("cvt.rna.tf32.f32 %0, %1;" : "=r"(u) : "f"(f));
    return u;
}
__device__ __forceinline__ void mma_tf32(float c[4], const uint32_t a[4],
                                         const uint32_t b[2]) {
    asm volatile(
        "mma.sync.aligned.m16n8k8.row.col.f32.tf32.tf32.f32 "
        "{%0,%1,%2,%3}, {%4,%5,%6,%7}, {%8,%9}, {%0,%1,%2,%3};"
        : "+f"(c[0]), "+f"(c[1]), "+f"(c[2]), "+f"(c[3])
        : "r"(a[0]), "r"(a[1]), "r"(a[2]), "r"(a[3]), "r"(b[0]), "r"(b[1]));
}
#define CP_ASYNC16(dst_smem, src_ptr) \
    asm volatile("cp.async.ca.shared.global [%0], [%1], 16;" \
                 :: "r"(dst_smem), "l"(src_ptr))
#define CP_COMMIT() asm volatile("cp.async.commit_group;")
#define CP_WAIT1()  asm volatile("cp.async.wait_group 1;")
#define CP_WAIT0()  asm volatile("cp.async.wait_group 0;")

// ---------------- edge prep -------------------------------------------------
__global__ void detect_dtype_kernel(const unsigned* __restrict__ w) {
    unsigned v = w[2 * threadIdx.x + 1];
    int any = __syncthreads_or(v != 0u);
    if (threadIdx.x == 0) g_is64 = (any == 0) ? 1 : 0;
}
__global__ void zero_deg_kernel() {
    int i = blockIdx.x * blockDim.x + threadIdx.x;
    if (i < NN) g_deg[i] = 0;
}
// convert + histogram fused
__global__ void convert_hist_kernel(const void* __restrict__ ei) {
    int e = blockIdx.x * blockDim.x + threadIdx.x;
    if (e >= ET) return;
    int s, d;
    if (e < EE) {
        if (g_is64) {
            const long long* p = (const long long*)ei;
            s = (int)p[e];
            d = (int)p[EE + e];
        } else {
            const int* p = (const int*)ei;
            s = p[e];
            d = p[EE + e];
        }
    } else {
        s = e - EE;   // self loop
        d = e - EE;
    }
    g_src[e] = s;
    g_dst[e] = d;
    atomicAdd(&g_deg[d], 1);
}

// ---------------- multi-block exclusive scan of g_deg -> g_off -------------
// phase 1: per-block (256 nodes) sum
__global__ __launch_bounds__(256)
void scan_p1_kernel() {
    __shared__ int sh[256];
    int i = blockIdx.x * 256 + threadIdx.x;
    sh[threadIdx.x] = (i < NN) ? g_deg[i] : 0;
    __syncthreads();
    for (int o = 128; o; o >>= 1) {
        if (threadIdx.x < o) sh[threadIdx.x] += sh[threadIdx.x + o];
        __syncthreads();
    }
    if (threadIdx.x == 0) g_bsum[blockIdx.x] = sh[0];
}
// phase 2: scan 196 block sums (1 tiny block)
__global__ __launch_bounds__(256)
void scan_p2_kernel() {
    __shared__ int sh[256];
    int tid = threadIdx.x;
    int v = (tid < NB) ? g_bsum[tid] : 0;
    sh[tid] = v;
    __syncthreads();
    for (int o = 1; o < 256; o <<= 1) {
        int t = (tid >= o) ? sh[tid - o] : 0;
        __syncthreads();
        sh[tid] += t;
        __syncthreads();
    }
    if (tid < NB) g_boff[tid] = sh[tid] - v;   // exclusive block offsets
    if (tid == 255) g_off[NN] = sh[255];       // total
}
// phase 3: local scan + block offset -> g_off; re-zero g_deg for scatter
__global__ __launch_bounds__(256)
void scan_p3_kernel() {
    __shared__ int sh[256];
    int tid = threadIdx.x;
    int i = blockIdx.x * 256 + tid;
    int v = (i < NN) ? g_deg[i] : 0;
    sh[tid] = v;
    __syncthreads();
    for (int o = 1; o < 256; o <<= 1) {
        int t = (tid >= o) ? sh[tid - o] : 0;
        __syncthreads();
        sh[tid] += t;
        __syncthreads();
    }
    if (i < NN) {
        g_off[i] = g_boff[blockIdx.x] + sh[tid] - v;
        g_deg[i] = 0;   // reuse as scatter cursor
    }
}
__global__ void scatter_kernel() {
    int e = blockIdx.x * blockDim.x + threadIdx.x;
    if (e >= ET) return;
    int d = g_dst[e];
    int pos = atomicAdd(&g_deg[d], 1);
    g_csr_src[g_off[d] + pos] = g_src[e];
}

// ---------------- bias fold: bias_eff = bo + bias_conv @ Wo^T --------------
__global__ void biaseff_kernel(const float* __restrict__ bias_conv,
                               const float* __restrict__ Wo,
                               const float* __restrict__ bo) {
    int c = threadIdx.x;
    if (c >= DD) return;
    float s = bo[c];
    for (int k = 0; k < HD; k++) s += bias_conv[k] * Wo[(size_t)c * HD + k];
    g_bias_eff[c] = s;
}

// ---------------- TF32 GEMM, dual weight/output sets -----------------------
// For blockIdx.y < ycnt: C0[M,OUT] = A @ W0^T + b0 (col block = y)
// else:                  C1[M,OUT] = A @ W1^T + b1 (col block = y - ycnt)
#define SMS 20
__global__ __launch_bounds__(256, 2)
void tf32_gemm_kernel(const float* __restrict__ A,
                      const float* __restrict__ W0, const float* __restrict__ b0v,
                      float* __restrict__ C0,
                      const float* __restrict__ W1, const float* __restrict__ b1v,
                      float* __restrict__ C1,
                      int M, int K, int OUT, int ycnt) {
    __shared__ float As[2][128 * SMS];
    __shared__ float Bs[2][128 * SMS];

    const float* W;  const float* bias;  float* C;
    int yb = blockIdx.y;
    if (yb < ycnt) { W = W0; bias = b0v; C = C0; }
    else           { W = W1; bias = b1v; C = C1; yb -= ycnt; }

    const int tid  = threadIdx.x;
    const int lane = tid & 31;
    const int wid  = tid >> 5;
    const int warpM = wid & 1;
    const int warpN = wid >> 1;
    const int gp = lane >> 2;
    const int tg = lane & 3;
    const int rowBlock = blockIdx.x * 128;
    const int colBlock = yb * 128;
    const int lr = tid >> 2;          // 0..63
    const int lc = (tid & 3) * 4;     // 0/4/8/12

    float acc[4][4][4];
#pragma unroll
    for (int mt = 0; mt < 4; mt++)
#pragma unroll
        for (int nt = 0; nt < 4; nt++)
#pragma unroll
            for (int r = 0; r < 4; r++) acc[mt][nt][r] = 0.f;

    auto load_stage = [&](int k0, int buf) {
#pragma unroll
        for (int h = 0; h < 2; h++) {
            int row  = lr + h * 64;
            int grow = rowBlock + row;
            float* sa = &As[buf][row * SMS + lc];
            if (grow < M) {
                CP_ASYNC16((uint32_t)__cvta_generic_to_shared(sa),
                           A + (size_t)grow * K + k0 + lc);
            } else {
                sa[0] = 0.f; sa[1] = 0.f; sa[2] = 0.f; sa[3] = 0.f;
            }
            float* sb = &Bs[buf][row * SMS + lc];
            CP_ASYNC16((uint32_t)__cvta_generic_to_shared(sb),
                       W + (size_t)(colBlock + row) * K + k0 + lc);
        }
    };

    const int nk = K >> 4;
    load_stage(0, 0);
    CP_COMMIT();

    for (int t = 0; t < nk; t++) {
        int cur = t & 1;
        if (t + 1 < nk) {
            load_stage((t + 1) << 4, (t + 1) & 1);
            CP_COMMIT();
            CP_WAIT1();
        } else {
            CP_WAIT0();
        }
        __syncthreads();

#pragma unroll
        for (int kk = 0; kk < 16; kk += 8) {
            uint32_t af[4][4], bf[4][2];
#pragma unroll
            for (int mt = 0; mt < 4; mt++) {
                int m0 = warpM * 64 + mt * 16;
                af[mt][0] = f2tf32(As[cur][(m0 + gp)     * SMS + kk + tg]);
                af[mt][1] = f2tf32(As[cur][(m0 + gp + 8) * SMS + kk + tg]);
                af[mt][2] = f2tf32(As[cur][(m0 + gp)     * SMS + kk + tg + 4]);
                af[mt][3] = f2tf32(As[cur][(m0 + gp + 8) * SMS + kk + tg + 4]);
            }
#pragma unroll
            for (int nt = 0; nt < 4; nt++) {
                int n0 = warpN * 32 + nt * 8;
                bf[nt][0] = f2tf32(Bs[cur][(n0 + gp) * SMS + kk + tg]);
                bf[nt][1] = f2tf32(Bs[cur][(n0 + gp) * SMS + kk + tg + 4]);
            }
#pragma unroll
            for (int mt = 0; mt < 4; mt++)
#pragma unroll
                for (int nt = 0; nt < 4; nt++)
                    mma_tf32(acc[mt][nt], af[mt], bf[nt]);
        }
        __syncthreads();
    }

    // epilogue
#pragma unroll
    for (int mt = 0; mt < 4; mt++) {
#pragma unroll
        for (int nt = 0; nt < 4; nt++) {
            int col  = colBlock + warpN * 32 + nt * 8 + tg * 2;
            float bb0 = bias[col], bb1 = bias[col + 1];
            int row0 = rowBlock + warpM * 64 + mt * 16 + gp;
            if (row0 < M) {
                float2 o = make_float2(acc[mt][nt][0] + bb0, acc[mt][nt][1] + bb1);
                *(float2*)(C + (size_t)row0 * OUT + col) = o;
            }
            int row1 = row0 + 8;
            if (row1 < M) {
                float2 o = make_float2(acc[mt][nt][2] + bb0, acc[mt][nt][3] + bb1);
                *(float2*)(C + (size_t)row1 * OUT + col) = o;
            }
        }
    }
}

// ---------------- fused GAT pass: one warp per destination node -------------
__global__ __launch_bounds__(256)
void gat_fused_kernel(const float* __restrict__ att) {
    int n = (blockIdx.x * blockDim.x + threadIdx.x) >> 5;
    int lane = threadIdx.x & 31;
    if (n >= NN) return;
    int off = lane * 8;

    const float4* pr = (const float4*)(g_xr + (size_t)n * HD + off);
    float4 b0 = pr[0], b1 = pr[1];
    float4 v0 = *(const float4*)(att + off);
    float4 v1 = *(const float4*)(att + off + 4);

    float acc[8] = {0, 0, 0, 0, 0, 0, 0, 0};
    float denom = 0.f;

    const int beg = g_off[n], end = g_off[n + 1];

    // 2-deep prefetch pipeline (every node has >= 1 neighbor: its self loop)
    float4 A0, A1, B0, B1;
    {
        int s0 = g_csr_src[beg];
        const float4* p0 = (const float4*)(g_xl + (size_t)s0 * HD + off);
        A0 = p0[0]; A1 = p0[1];
    }
    if (beg + 1 < end) {
        int s1 = g_csr_src[beg + 1];
        const float4* p1 = (const float4*)(g_xl + (size_t)s1 * HD + off);
        B0 = p1[0]; B1 = p1[1];
    }

    for (int i = beg; i < end; i++) {
        float4 c0 = A0, c1 = A1;
        A0 = B0; A1 = B1;
        if (i + 2 < end) {
            int sn = g_csr_src[i + 2];
            const float4* pn = (const float4*)(g_xl + (size_t)sn * HD + off);
            B0 = pn[0]; B1 = pn[1];
        }
        float t = lrelu(c0.x + b0.x) * v0.x + lrelu(c0.y + b0.y) * v0.y +
                  lrelu(c0.z + b0.z) * v0.z + lrelu(c0.w + b0.w) * v0.w +
                  lrelu(c1.x + b1.x) * v1.x + lrelu(c1.y + b1.y) * v1.y +
                  lrelu(c1.z + b1.z) * v1.z + lrelu(c1.w + b1.w) * v1.w;
#pragma unroll
        for (int o = 8; o; o >>= 1) t += __shfl_xor_sync(0xFFFFFFFFu, t, o);
        float ex = __expf(fminf(t, 80.f));
        acc[0] = fmaf(ex, c0.x, acc[0]);
        acc[1] = fmaf(ex, c0.y, acc[1]);
        acc[2] = fmaf(ex, c0.z, acc[2]);
        acc[3] = fmaf(ex, c0.w, acc[3]);
        acc[4] = fmaf(ex, c1.x, acc[4]);
        acc[5] = fmaf(ex, c1.y, acc[5]);
        acc[6] = fmaf(ex, c1.z, acc[6]);
        acc[7] = fmaf(ex, c1.w, acc[7]);
        denom += ex;
    }

    float inv = 1.f / (denom + 1e-16f);
    float4 o0 = make_float4(acc[0] * inv, acc[1] * inv, acc[2] * inv, acc[3] * inv);
    float4 o1 = make_float4(acc[4] * inv, acc[5] * inv, acc[6] * inv, acc[7] * inv);
    float4* po = (float4*)(g_agg + (size_t)n * HD + off);
    po[0] = o0;
    po[1] = o1;
}

// ---------------- launch ---------------------------------------------------
extern "C" void kernel_launch(void* const* d_in, const int* in_sizes, int n_in,
                              void* d_out, int out_size) {
    const float* x         = (const float*)d_in[0];
    const void*  edge      = d_in[1];
    const float* Wl        = (const float*)d_in[2];
    const float* bl        = (const float*)d_in[3];
    const float* Wr        = (const float*)d_in[4];
    const float* br        = (const float*)d_in[5];
    const float* att       = (const float*)d_in[6];
    const float* bias_conv = (const float*)d_in[7];
    const float* Wo        = (const float*)d_in[8];
    const float* bo        = (const float*)d_in[9];
    float* out = (float*)d_out;

    float* xl;   cudaGetSymbolAddress((void**)&xl,   g_xl);
    float* xr;   cudaGetSymbolAddress((void**)&xr,   g_xr);
    float* agg;  cudaGetSymbolAddress((void**)&agg,  g_agg);
    float* beff; cudaGetSymbolAddress((void**)&beff, g_bias_eff);

    // One-time side stream + events (no device-memory allocation involved).
    static cudaStream_t s_side = nullptr;
    static cudaEvent_t  s_fork = nullptr, s_join = nullptr;
    if (!s_side) {
        cudaStreamCreateWithFlags(&s_side, cudaStreamNonBlocking);
        cudaEventCreateWithFlags(&s_fork, cudaEventDisableTiming);
        cudaEventCreateWithFlags(&s_join, cudaEventDisableTiming);
    }

    // -------- fork: projections (side) || CSR build (main) --------
    cudaEventRecord(s_fork, 0);
    cudaStreamWaitEvent(s_side, s_fork, 0);

    // side stream: bias fold + node projections (xl, xr)
    biaseff_kernel<<<1, 128, 0, s_side>>>(bias_conv, Wo, bo);
    {
        dim3 grid((NN + 127) / 128, 4);
        tf32_gemm_kernel<<<grid, 256, 0, s_side>>>(x, Wl, bl, xl, Wr, br, xr,
                                                   NN, DD, HD, 2);
    }

    // main stream: edges -> int32 (+self loops) + histogram -> scan -> CSR
    detect_dtype_kernel<<<1, 256>>>((const unsigned*)edge);
    zero_deg_kernel<<<(NN + 255) / 256, 256>>>();
    convert_hist_kernel<<<(ET + 255) / 256, 256>>>(edge);
    scan_p1_kernel<<<NB, 256>>>();
    scan_p2_kernel<<<1, 256>>>();
    scan_p3_kernel<<<NB, 256>>>();
    scatter_kernel<<<(ET + 255) / 256, 256>>>();

    // -------- join --------
    cudaEventRecord(s_join, s_side);
    cudaStreamWaitEvent(0, s_join, 0);

    // fused: score -> exp -> weighted aggregate (one warp per node)
    gat_fused_kernel<<<(NN * 32 + 255) / 256, 256>>>(att);

    // output projection: out = agg @ Wo^T + bias_eff
    {
        dim3 grid((NN + 127) / 128, 1);
        tf32_gemm_kernel<<<grid, 256>>>(agg, Wo, beff, out, Wo, beff, out,
                                        NN, HD, DD, 1);
    }
}